// round 12
// baseline (speedup 1.0000x reference)
#include <cuda_runtime.h>
#include <cuda_fp16.h>
#include <cstdint>

#define NLAYERS 25
#define KOUT 50
#define FW 1266
#define ROWS 64
#define THREADS 512
#define MAXKS 76
#define NT 7
#define RSE 1272                         // fp16 elems/row (2544B, 16B-aligned)
#define A_BYTES (ROWS * RSE * 2)         // 162816
#define WOFF A_BYTES
#define KSB 1792                         // per-ks W block: 7 nt * 32 lanes * 8B
#define WBUF (8 * KSB)                   // 14336 (8-ks chunk)
#define NBUF 3
#define SCOFF (WOFF + NBUF * WBUF)       // 205824 (dedicated kg-reduction scratch)
#define SMEM_TOTAL (SCOFF + 16384)       // 222208

// W fragments: [layer][ks(76)][nt(7)][lane(32)][word(2)]; word = {bhi_r0, bhi_r1}
#define WFRAG_WORDS (NLAYERS * MAXKS * NT * 32 * 2)   // 851,200 (3.4 MB)
__device__ uint32_t g_wfrag[WFRAG_WORDS];

__device__ __forceinline__ uint32_t packh2(__half a, __half b) {
    return (uint32_t)__half_as_ushort(a) | ((uint32_t)__half_as_ushort(b) << 16);
}

// ---- prekernel: fp32 W -> fragment-ordered fp16 pairs (identical to R10) ----
__global__ void stage_w_kernel(const float* __restrict__ Ws) {
    int i = blockIdx.x * blockDim.x + threadIdx.x;
    if (i >= WFRAG_WORDS) return;
    int w = i;
    int reg  = w & 1;  w >>= 1;
    int ln   = w & 31; w >>= 5;
    int nt   = w % NT; w /= NT;
    int ks   = w % MAXKS;
    int layer = w / MAXKS;
    int n = nt * 8 + (ln >> 2);
    int k = ks * 16 + ((ln & 3) << 1) + reg * 8;   // k <= 1214, in-bounds
    float w0 = 0.f, w1 = 0.f;
    if (n < KOUT) {
        const float* p = Ws + ((size_t)layer * KOUT + n) * FW + k;
        w0 = p[0]; w1 = p[1];
    }
    g_wfrag[i] = packh2(__float2half_rn(w0), __float2half_rn(w1));
}

#define MMA(d, a, b0_, b1_) \
    asm volatile("mma.sync.aligned.m16n8k16.row.col.f32.f16.f16.f32 " \
        "{%0,%1,%2,%3},{%4,%5,%6,%7},{%8,%9},{%0,%1,%2,%3};" \
        : "+f"(d[0]), "+f"(d[1]), "+f"(d[2]), "+f"(d[3]) \
        : "r"(a[0]), "r"(a[1]), "r"(a[2]), "r"(a[3]), "r"(b0_), "r"(b1_))

#define LDSM4(r, addr) \
    asm volatile("ldmatrix.sync.aligned.m8n8.x4.shared.b16 {%0,%1,%2,%3}, [%4];" \
        : "=r"(r[0]), "=r"(r[1]), "=r"(r[2]), "=r"(r[3]) : "r"(addr))

__device__ __forceinline__ void cp16(uint32_t dst, const void* src) {
    asm volatile("cp.async.cg.shared.global [%0], [%1], 16;" :: "r"(dst), "l"(src));
}
#define COMMIT() asm volatile("cp.async.commit_group;")

__global__ void __launch_bounds__(THREADS, 1) value_model_mma_kernel(
    const float* __restrict__ state,
    const float* __restrict__ bs,
    const float* __restrict__ Wout,
    const float* __restrict__ bout,
    float* __restrict__ out)
{
    extern __shared__ char smraw[];
    __half* A = (__half*)smraw;
    const uint32_t sm_u32 = (uint32_t)__cvta_generic_to_shared(smraw);

    const int tid  = threadIdx.x;
    const int lane = tid & 31;
    const int wid  = tid >> 5;
    const int cta  = blockIdx.x;
    const int kg   = wid >> 2;         // 0..3: k-split within 8-ks chunk (2 ks each)
    const int m    = (wid >> 1) & 1;   // row-half: rows m*32 .. m*32+31
    const int ng   = wid & 1;          // n-group: tiles ng*4 .. (<7)
    const int sub  = wid & 3;          // (m, ng) id

    // ---- zero A plane ----
    {
        uint4 z = make_uint4(0u, 0u, 0u, 0u);
        uint4* p = (uint4*)smraw;
        for (int i = tid; i < A_BYTES / 16; i += THREADS) p[i] = z;
    }
    __syncthreads();

    // ---- initial state (64 x 16) ----
    for (int idx = tid; idx < ROWS * 16; idx += THREADS) {
        int r = idx >> 4, j = idx & 15;
        A[r * RSE + j] = __float2half_rn(state[(cta * ROWS + r) * 16 + j]);
    }
    __syncthreads();

    // ldmatrix base for this warp's two m16 tiles (rows m*32 and m*32+16)
    const uint32_t abase = sm_u32 + (uint32_t)((m * 32 + (lane & 15)) * RSE) * 2u
                                  + (uint32_t)(lane >> 4) * 16u;
    const uint32_t wsm = sm_u32 + WOFF;
    float4* scratch4 = (float4*)(smraw + SCOFF);   // dedicated (W ring stays live)

    // ---- layer-0 prologue: stage chunk0, commit; commit empty (chunk1 slot) ----
    {
        const int nks0 = 1;   // layer 0: width 16 -> 1 ks
        const char* wsrc = (const char*)g_wfrag;
        for (int i = tid; i < nks0 * 112; i += THREADS)
            cp16(wsm + i * 16, wsrc + (size_t)i * 16);
        COMMIT();
        COMMIT();   // empty chunk-1 group (nc=1 for layer 0)
    }

    int width = 16;
    for (int l = 0; l < NLAYERS; l++) {
        const int nks = (width + 15) >> 4;
        const int nc  = (nks + 7) >> 3;
        const char* wsrc = (const char*)g_wfrag + (size_t)(l * MAXKS) * KSB;

        float acc[2][4][4] = {};

        for (int c = 0; c < nc; c++) {
            // chunk c's group: all but 1 newest (positional, empty groups count)
            asm volatile("cp.async.wait_group 1;" ::: "memory");
            __syncthreads();   // publish c; proves all reads of chunk c-1 done

            // stage chunk c+2 into buffer (c+2)%3 == (c-1)%3 (freed by the barrier above)
            if (c + 2 < nc) {
                const int rem = nks - (c + 2) * 8;
                const int ksn2 = (rem < 8) ? rem : 8;
                const char* src = wsrc + (size_t)((c + 2) * 8) * KSB;
                uint32_t dst = wsm + (uint32_t)((c + 2) % NBUF) * WBUF;
                for (int i = tid; i < ksn2 * 112; i += THREADS)
                    cp16(dst + i * 16, src + (size_t)i * 16);
            }
            COMMIT();          // real or empty: uniform group positioning

            // ---- compute chunk c: hoist ALL loads, then all MMAs ----
            const uint32_t* wb = (const uint32_t*)(smraw + WOFF + (size_t)(c % NBUF) * WBUF);
            const int ksn = min(8, nks - c * 8);
            const int bk = kg * 2;

            uint32_t a0[2][4], a1[2][4];
            uint2 bfr[2][4];
            #pragma unroll
            for (int i = 0; i < 2; i++) {
                const int ksl = bk + i;
                if (ksl < ksn) {
                    const int ks = c * 8 + ksl;
                    const uint32_t ad = abase + (uint32_t)ks * 32u;
                    LDSM4(a0[i], ad);
                    LDSM4(a1[i], ad + 16u * RSE * 2u);
                    const uint32_t* wk = wb + ksl * 448;
                    #pragma unroll
                    for (int t = 0; t < 4; t++) {
                        if (ng * 4 + t < NT)
                            bfr[i][t] = *(const uint2*)(wk + (ng * 4 + t) * 64 + lane * 2);
                    }
                }
            }
            #pragma unroll
            for (int i = 0; i < 2; i++) {
                const int ksl = bk + i;
                if (ksl < ksn) {
                    #pragma unroll
                    for (int t = 0; t < 4; t++) {
                        if (ng * 4 + t < NT) {
                            MMA(acc[0][t], a0[i], bfr[i][t].x, bfr[i][t].y);
                            MMA(acc[1][t], a1[i], bfr[i][t].x, bfr[i][t].y);
                        }
                    }
                }
            }
            // no trailing barrier: next iter's top barrier frees this buffer
        }

        // ---- epilogue: 3-wave kg-reduction; next-layer prologue hidden in wave 1 ----
        #pragma unroll
        for (int q = 1; q <= 3; q++) {
            if (kg == q) {
                #pragma unroll
                for (int mt = 0; mt < 2; mt++)
                    #pragma unroll
                    for (int t = 0; t < 4; t++)
                        scratch4[sub * 256 + (mt * 4 + t) * 32 + lane] =
                            make_float4(acc[mt][t][0], acc[mt][t][1],
                                        acc[mt][t][2], acc[mt][t][3]);
            }
            __syncthreads();
            if (q == 1 && l + 1 < NLAYERS) {
                // stage next layer's chunks 0,1 (overlaps remaining epilogue waves)
                const int nnks = (width + KOUT + 15) >> 4;
                const char* nsrc = (const char*)g_wfrag + (size_t)((l + 1) * MAXKS) * KSB;
                const int k0 = (nnks < 8) ? nnks : 8;
                for (int i = tid; i < k0 * 112; i += THREADS)
                    cp16(wsm + i * 16, nsrc + (size_t)i * 16);
                COMMIT();
                if (nnks > 8) {
                    const int rem = nnks - 8;
                    const int k1 = (rem < 8) ? rem : 8;
                    for (int i = tid; i < k1 * 112; i += THREADS)
                        cp16(wsm + WBUF + i * 16, nsrc + (size_t)(8 * KSB) + (size_t)i * 16);
                }
                COMMIT();
            }
            if (kg == 0) {
                #pragma unroll
                for (int mt = 0; mt < 2; mt++)
                    #pragma unroll
                    for (int t = 0; t < 4; t++) {
                        float4 v = scratch4[sub * 256 + (mt * 4 + t) * 32 + lane];
                        acc[mt][t][0] += v.x; acc[mt][t][1] += v.y;
                        acc[mt][t][2] += v.z; acc[mt][t][3] += v.w;
                    }
            }
            __syncthreads();
        }

        if (kg == 0) {
            #pragma unroll
            for (int mt = 0; mt < 2; mt++)
                #pragma unroll
                for (int t = 0; t < 4; t++) {
                    const int tile = ng * 4 + t;
                    if (tile < NT) {
                        const int n0 = tile * 8 + ((lane & 3) << 1);
                        const int rbase = m * 32 + mt * 16 + (lane >> 2);
                        #pragma unroll
                        for (int half = 0; half < 2; half++) {
                            const int n = n0 + half;
                            if (n < KOUT) {
                                const float bz = bs[l * KOUT + n];
                                #pragma unroll
                                for (int rr = 0; rr < 2; rr++) {
                                    float y = acc[mt][t][rr * 2 + half] + bz;
                                    y = (y > 0.f) ? y : 0.01f * y;
                                    A[(rbase + rr * 8) * RSE + width + n] =
                                        __float2half_rn(y);
                                }
                            }
                        }
                    }
                }
        }
        width += KOUT;
        // no layer-end barrier: next layer's first top barrier orders A writes
    }

    __syncthreads();

    // ---- final projection: out[r] = x . Wout + bout ----
    #pragma unroll
    for (int t = 0; t < 4; t++) {
        const int r = wid * 4 + t;
        float s = 0.f;
        for (int j = lane; j < FW; j += 32)
            s += __half2float(A[r * RSE + j]) * Wout[j];
        #pragma unroll
        for (int o = 16; o; o >>= 1) s += __shfl_xor_sync(0xffffffffu, s, o);
        if (lane == 0) out[cta * ROWS + r] = s + bout[0];
    }
}

extern "C" void kernel_launch(void* const* d_in, const int* in_sizes, int n_in,
                              void* d_out, int out_size) {
    const float* state = (const float*)d_in[0];
    const float* Ws    = (const float*)d_in[1];
    const float* bs    = (const float*)d_in[2];
    const float* Wout  = (const float*)d_in[3];
    const float* bout  = (const float*)d_in[4];
    float* out = (float*)d_out;

    const int B = in_sizes[0] / 16;   // 32768

    stage_w_kernel<<<(WFRAG_WORDS + 255) / 256, 256>>>(Ws);

    cudaFuncSetAttribute(value_model_mma_kernel,
                         cudaFuncAttributeMaxDynamicSharedMemorySize, SMEM_TOTAL);
    value_model_mma_kernel<<<B / ROWS, THREADS, SMEM_TOTAL>>>(state, bs, Wout, bout, out);
}

// round 13
// speedup vs baseline: 1.2304x; 1.2304x over previous
#include <cuda_runtime.h>
#include <cuda_fp16.h>
#include <cstdint>

#define NLAYERS 25
#define KOUT 50
#define FW 1266
#define ROWS 64
#define THREADS 512
#define MAXKS 76
#define NT 7
#define RSE 1272                         // fp16 elems/row (2544B, 16B-aligned)
#define A_BYTES (ROWS * RSE * 2)         // 162816
#define WOFF A_BYTES
#define KSB 1792                         // per-ks W block: 7 nt * 32 lanes * 8B
#define CK 16                            // ks per chunk
#define WBUF (CK * KSB)                  // 28672
#define SMEM_TOTAL (WOFF + 2 * WBUF)     // 220160

// W fragments: [layer][ks(76)][nt(7)][lane(32)][word(2)]; word = {bhi_r0, bhi_r1}
#define WFRAG_WORDS (NLAYERS * MAXKS * NT * 32 * 2)   // 851,200 (3.4 MB)
__device__ uint32_t g_wfrag[WFRAG_WORDS];

__device__ __forceinline__ uint32_t packh2(__half a, __half b) {
    return (uint32_t)__half_as_ushort(a) | ((uint32_t)__half_as_ushort(b) << 16);
}

// ---- prekernel: fp32 W -> fragment-ordered fp16 pairs (identical to R10) ----
__global__ void stage_w_kernel(const float* __restrict__ Ws) {
    int i = blockIdx.x * blockDim.x + threadIdx.x;
    if (i >= WFRAG_WORDS) return;
    int w = i;
    int reg  = w & 1;  w >>= 1;
    int ln   = w & 31; w >>= 5;
    int nt   = w % NT; w /= NT;
    int ks   = w % MAXKS;
    int layer = w / MAXKS;
    int n = nt * 8 + (ln >> 2);
    int k = ks * 16 + ((ln & 3) << 1) + reg * 8;   // k <= 1214, in-bounds
    float w0 = 0.f, w1 = 0.f;
    if (n < KOUT) {
        const float* p = Ws + ((size_t)layer * KOUT + n) * FW + k;
        w0 = p[0]; w1 = p[1];
    }
    g_wfrag[i] = packh2(__float2half_rn(w0), __float2half_rn(w1));
}

#define MMA(d, a, b0_, b1_) \
    asm volatile("mma.sync.aligned.m16n8k16.row.col.f32.f16.f16.f32 " \
        "{%0,%1,%2,%3},{%4,%5,%6,%7},{%8,%9},{%0,%1,%2,%3};" \
        : "+f"(d[0]), "+f"(d[1]), "+f"(d[2]), "+f"(d[3]) \
        : "r"(a[0]), "r"(a[1]), "r"(a[2]), "r"(a[3]), "r"(b0_), "r"(b1_))

#define LDSM4(r, addr) \
    asm volatile("ldmatrix.sync.aligned.m8n8.x4.shared.b16 {%0,%1,%2,%3}, [%4];" \
        : "=r"(r[0]), "=r"(r[1]), "=r"(r[2]), "=r"(r[3]) : "r"(addr))

__device__ __forceinline__ void cp16(uint32_t dst, const void* src) {
    asm volatile("cp.async.cg.shared.global [%0], [%1], 16;" :: "r"(dst), "l"(src));
}

__global__ void __launch_bounds__(THREADS, 1) value_model_mma_kernel(
    const float* __restrict__ state,
    const float* __restrict__ bs,
    const float* __restrict__ Wout,
    const float* __restrict__ bout,
    float* __restrict__ out)
{
    extern __shared__ char smraw[];
    __half* A = (__half*)smraw;
    const uint32_t sm_u32 = (uint32_t)__cvta_generic_to_shared(smraw);

    const int tid  = threadIdx.x;
    const int lane = tid & 31;
    const int wid  = tid >> 5;
    const int cta  = blockIdx.x;
    const int kg   = wid >> 2;         // 0..3: k-split within 16-ks chunk (4 ks each)
    const int m    = (wid >> 1) & 1;   // row-half: rows m*32 .. m*32+31
    const int ng   = wid & 1;          // n-group: tiles ng*4 .. (<7)
    const int sub  = wid & 3;          // (m, ng) id

    // ---- zero A plane ----
    {
        uint4 z = make_uint4(0u, 0u, 0u, 0u);
        uint4* p = (uint4*)smraw;
        for (int i = tid; i < A_BYTES / 16; i += THREADS) p[i] = z;
    }
    __syncthreads();

    // ---- initial state (64 x 16) ----
    for (int idx = tid; idx < ROWS * 16; idx += THREADS) {
        int r = idx >> 4, j = idx & 15;
        A[r * RSE + j] = __float2half_rn(state[(cta * ROWS + r) * 16 + j]);
    }
    __syncthreads();

    // ldmatrix base for this warp's two m16 tiles (rows m*32 and m*32+16)
    const uint32_t abase = sm_u32 + (uint32_t)((m * 32 + (lane & 15)) * RSE) * 2u
                                  + (uint32_t)(lane >> 4) * 16u;
    const uint32_t wsm = sm_u32 + WOFF;
    float4* scratch4 = (float4*)(smraw + WOFF);   // overlays W buffers (dead at epilogue)

    int width = 16;
    for (int l = 0; l < NLAYERS; l++) {
        const int nks = (width + 15) >> 4;
        const int nc  = (nks + CK - 1) / CK;

        float acc[2][4][4] = {};

        // prologue: stage chunk 0
        {
            const int ksn0 = (nks < CK) ? nks : CK;
            const char* src = (const char*)g_wfrag + (size_t)(l * MAXKS) * KSB;
            const int nops = ksn0 * 112;
            for (int i = tid; i < nops; i += THREADS) cp16(wsm + i * 16, src + (size_t)i * 16);
            asm volatile("cp.async.commit_group;");
        }

        for (int c = 0; c < nc; c++) {
            if (c + 1 < nc) {
                const int rem = nks - (c + 1) * CK;
                const int ksn1 = (rem < CK) ? rem : CK;
                const char* src = (const char*)g_wfrag
                                + (size_t)(l * MAXKS + (c + 1) * CK) * KSB;
                uint32_t dst = wsm + (((c + 1) & 1) ? WBUF : 0);
                const int nops = ksn1 * 112;
                for (int i = tid; i < nops; i += THREADS) cp16(dst + i * 16, src + (size_t)i * 16);
                asm volatile("cp.async.commit_group;");
                asm volatile("cp.async.wait_group 1;");
            } else {
                asm volatile("cp.async.wait_group 0;");
            }
            __syncthreads();

            const uint32_t* wb = (const uint32_t*)(smraw + WOFF + ((c & 1) ? WBUF : 0));
            const int ksn = min(CK, nks - c * CK);

            #pragma unroll
            for (int i = 0; i < 4; i++) {
                const int ksl = kg * 4 + i;
                if (ksl < ksn) {
                    const int ks = c * CK + ksl;
                    uint32_t a0[4], a1[4];
                    const uint32_t ad = abase + (uint32_t)ks * 32u;
                    LDSM4(a0, ad);
                    LDSM4(a1, ad + 16u * RSE * 2u);
                    const uint32_t* wk = wb + ksl * 448;
                    #pragma unroll
                    for (int t = 0; t < 4; t++) {
                        const int tile = ng * 4 + t;
                        if (tile < NT) {
                            const uint2 b = *(const uint2*)(wk + tile * 64 + lane * 2);
                            MMA(acc[0][t], a0, b.x, b.y);
                            MMA(acc[1][t], a1, b.x, b.y);
                        }
                    }
                }
            }
            __syncthreads();
        }

        // ---- epilogue: 3-wave kg-reduction (16KB scratch overlay), bias + leaky, append ----
        #pragma unroll
        for (int q = 1; q <= 3; q++) {
            if (kg == q) {
                #pragma unroll
                for (int mt = 0; mt < 2; mt++)
                    #pragma unroll
                    for (int t = 0; t < 4; t++)
                        scratch4[sub * 256 + (mt * 4 + t) * 32 + lane] =
                            make_float4(acc[mt][t][0], acc[mt][t][1],
                                        acc[mt][t][2], acc[mt][t][3]);
            }
            __syncthreads();
            if (kg == 0) {
                #pragma unroll
                for (int mt = 0; mt < 2; mt++)
                    #pragma unroll
                    for (int t = 0; t < 4; t++) {
                        float4 v = scratch4[sub * 256 + (mt * 4 + t) * 32 + lane];
                        acc[mt][t][0] += v.x; acc[mt][t][1] += v.y;
                        acc[mt][t][2] += v.z; acc[mt][t][3] += v.w;
                    }
            }
            __syncthreads();
        }

        if (kg == 0) {
            #pragma unroll
            for (int mt = 0; mt < 2; mt++)
                #pragma unroll
                for (int t = 0; t < 4; t++) {
                    const int tile = ng * 4 + t;
                    if (tile < NT) {
                        const int n0 = tile * 8 + ((lane & 3) << 1);
                        const int rbase = m * 32 + mt * 16 + (lane >> 2);
                        #pragma unroll
                        for (int half = 0; half < 2; half++) {
                            const int n = n0 + half;
                            if (n < KOUT) {
                                const float bz = bs[l * KOUT + n];
                                #pragma unroll
                                for (int rr = 0; rr < 2; rr++) {
                                    float y = acc[mt][t][rr * 2 + half] + bz;
                                    y = (y > 0.f) ? y : 0.01f * y;
                                    A[(rbase + rr * 8) * RSE + width + n] =
                                        __float2half_rn(y);
                                }
                            }
                        }
                    }
                }
        }
        width += KOUT;
        __syncthreads();
    }

    // ---- final projection: out[r] = x . Wout + bout ----
    #pragma unroll
    for (int t = 0; t < 4; t++) {
        const int r = wid * 4 + t;
        float s = 0.f;
        for (int j = lane; j < FW; j += 32)
            s += __half2float(A[r * RSE + j]) * Wout[j];
        #pragma unroll
        for (int o = 16; o; o >>= 1) s += __shfl_xor_sync(0xffffffffu, s, o);
        if (lane == 0) out[cta * ROWS + r] = s + bout[0];
    }
}

extern "C" void kernel_launch(void* const* d_in, const int* in_sizes, int n_in,
                              void* d_out, int out_size) {
    const float* state = (const float*)d_in[0];
    const float* Ws    = (const float*)d_in[1];
    const float* bs    = (const float*)d_in[2];
    const float* Wout  = (const float*)d_in[3];
    const float* bout  = (const float*)d_in[4];
    float* out = (float*)d_out;

    const int B = in_sizes[0] / 16;   // 32768

    stage_w_kernel<<<(WFRAG_WORDS + 255) / 256, 256>>>(Ws);

    cudaFuncSetAttribute(value_model_mma_kernel,
                         cudaFuncAttributeMaxDynamicSharedMemorySize, SMEM_TOTAL);
    value_model_mma_kernel<<<B / ROWS, THREADS, SMEM_TOTAL>>>(state, bs, Wout, bout, out);
}

// round 14
// speedup vs baseline: 1.3315x; 1.0821x over previous
#include <cuda_runtime.h>
#include <cuda_fp16.h>
#include <cstdint>

#define NLAYERS 25
#define KOUT 50
#define FW 1266
#define ROWS 64
#define THREADS 512
#define MAXKS 76
#define NT 7
#define RSE 1272                         // fp16 elems/row (2544B, 16B-aligned)
#define A_BYTES (ROWS * RSE * 2)         // 162816
#define WOFF A_BYTES
#define KSB 1792                         // per-ks W block: 7 nt * 32 lanes * 8B
#define CK 16                            // ks per chunk
#define WBUF (CK * KSB)                  // 28672
#define SMEM_TOTAL (WOFF + 2 * WBUF)     // 220160

// W fragments: [layer][ks(76)][nt(7)][lane(32)][word(2)]; word = {bhi_r0, bhi_r1}
#define WFRAG_WORDS (NLAYERS * MAXKS * NT * 32 * 2)   // 851,200 (3.4 MB)
__device__ uint32_t g_wfrag[WFRAG_WORDS];

__device__ __forceinline__ uint32_t packh2(__half a, __half b) {
    return (uint32_t)__half_as_ushort(a) | ((uint32_t)__half_as_ushort(b) << 16);
}

// ---- prekernel: fp32 W -> fragment-ordered fp16 pairs (identical to R10/R13) ----
__global__ void stage_w_kernel(const float* __restrict__ Ws) {
    int i = blockIdx.x * blockDim.x + threadIdx.x;
    if (i >= WFRAG_WORDS) return;
    int w = i;
    int reg  = w & 1;  w >>= 1;
    int ln   = w & 31; w >>= 5;
    int nt   = w % NT; w /= NT;
    int ks   = w % MAXKS;
    int layer = w / MAXKS;
    int n = nt * 8 + (ln >> 2);
    int k = ks * 16 + ((ln & 3) << 1) + reg * 8;   // k <= 1214, in-bounds
    float w0 = 0.f, w1 = 0.f;
    if (n < KOUT) {
        const float* p = Ws + ((size_t)layer * KOUT + n) * FW + k;
        w0 = p[0]; w1 = p[1];
    }
    g_wfrag[i] = packh2(__float2half_rn(w0), __float2half_rn(w1));
}

#define MMA(d, a, b0_, b1_) \
    asm volatile("mma.sync.aligned.m16n8k16.row.col.f32.f16.f16.f32 " \
        "{%0,%1,%2,%3},{%4,%5,%6,%7},{%8,%9},{%0,%1,%2,%3};" \
        : "+f"(d[0]), "+f"(d[1]), "+f"(d[2]), "+f"(d[3]) \
        : "r"(a[0]), "r"(a[1]), "r"(a[2]), "r"(a[3]), "r"(b0_), "r"(b1_))

#define LDSM4(r, addr) \
    asm volatile("ldmatrix.sync.aligned.m8n8.x4.shared.b16 {%0,%1,%2,%3}, [%4];" \
        : "=r"(r[0]), "=r"(r[1]), "=r"(r[2]), "=r"(r[3]) : "r"(addr))

__device__ __forceinline__ void cp16(uint32_t dst, const void* src) {
    asm volatile("cp.async.cg.shared.global [%0], [%1], 16;" :: "r"(dst), "l"(src));
}

__global__ void __launch_bounds__(THREADS, 1) value_model_mma_kernel(
    const float* __restrict__ state,
    const float* __restrict__ bs,
    const float* __restrict__ Wout,
    const float* __restrict__ bout,
    float* __restrict__ out)
{
    extern __shared__ char smraw[];
    __half* A = (__half*)smraw;
    const uint32_t sm_u32 = (uint32_t)__cvta_generic_to_shared(smraw);

    const int tid  = threadIdx.x;
    const int lane = tid & 31;
    const int wid  = tid >> 5;
    const int cta  = blockIdx.x;
    const int kg   = wid >> 2;         // 0..3: k-split within 16-ks chunk (4 ks each)
    const int m    = (wid >> 1) & 1;   // row-half: rows m*32 .. m*32+31
    const int ng   = wid & 1;          // n-group: tiles ng*4 .. (<7)
    const int sub  = wid & 3;          // (m, ng) id

    // ---- zero A plane ----
    {
        uint4 z = make_uint4(0u, 0u, 0u, 0u);
        uint4* p = (uint4*)smraw;
        for (int i = tid; i < A_BYTES / 16; i += THREADS) p[i] = z;
    }
    __syncthreads();

    // ---- initial state (64 x 16) ----
    for (int idx = tid; idx < ROWS * 16; idx += THREADS) {
        int r = idx >> 4, j = idx & 15;
        A[r * RSE + j] = __float2half_rn(state[(cta * ROWS + r) * 16 + j]);
    }
    __syncthreads();

    // ldmatrix base for this warp's two m16 tiles (rows m*32 and m*32+16)
    const uint32_t abase = sm_u32 + (uint32_t)((m * 32 + (lane & 15)) * RSE) * 2u
                                  + (uint32_t)(lane >> 4) * 16u;
    const uint32_t wsm = sm_u32 + WOFF;
    // single-wave kg-reduction scratch: 12 slots x 256 float4 = 48KB, overlays
    // BOTH dead W buffers at epilogue time
    float4* scratch4 = (float4*)(smraw + WOFF);

    int width = 16;
    for (int l = 0; l < NLAYERS; l++) {
        const int nks = (width + 15) >> 4;
        const int nc  = (nks + CK - 1) / CK;

        float acc[2][4][4] = {};

        // prologue: stage chunk 0
        {
            const int ksn0 = (nks < CK) ? nks : CK;
            const char* src = (const char*)g_wfrag + (size_t)(l * MAXKS) * KSB;
            const int nops = ksn0 * 112;
            for (int i = tid; i < nops; i += THREADS) cp16(wsm + i * 16, src + (size_t)i * 16);
            asm volatile("cp.async.commit_group;");
        }

        for (int c = 0; c < nc; c++) {
            if (c + 1 < nc) {
                const int rem = nks - (c + 1) * CK;
                const int ksn1 = (rem < CK) ? rem : CK;
                const char* src = (const char*)g_wfrag
                                + (size_t)(l * MAXKS + (c + 1) * CK) * KSB;
                uint32_t dst = wsm + (((c + 1) & 1) ? WBUF : 0);
                const int nops = ksn1 * 112;
                for (int i = tid; i < nops; i += THREADS) cp16(dst + i * 16, src + (size_t)i * 16);
                asm volatile("cp.async.commit_group;");
                asm volatile("cp.async.wait_group 1;");
            } else {
                asm volatile("cp.async.wait_group 0;");
            }
            __syncthreads();

            const uint32_t* wb = (const uint32_t*)(smraw + WOFF + ((c & 1) ? WBUF : 0));
            const int ksn = min(CK, nks - c * CK);

            #pragma unroll
            for (int i = 0; i < 4; i++) {
                const int ksl = kg * 4 + i;
                if (ksl < ksn) {
                    const int ks = c * CK + ksl;
                    uint32_t a0[4], a1[4];
                    const uint32_t ad = abase + (uint32_t)ks * 32u;
                    LDSM4(a0, ad);
                    LDSM4(a1, ad + 16u * RSE * 2u);
                    const uint32_t* wk = wb + ksl * 448;
                    #pragma unroll
                    for (int t = 0; t < 4; t++) {
                        const int tile = ng * 4 + t;
                        if (tile < NT) {
                            const uint2 b = *(const uint2*)(wk + tile * 64 + lane * 2);
                            MMA(acc[0][t], a0, b.x, b.y);
                            MMA(acc[1][t], a1, b.x, b.y);
                        }
                    }
                }
            }
            __syncthreads();
        }

        // ---- epilogue: SINGLE-WAVE kg-reduction (48KB overlay), bias + leaky, append ----
        if (kg != 0) {
            float4* slot = scratch4 + ((kg - 1) * 4 + sub) * 256;
            #pragma unroll
            for (int mt = 0; mt < 2; mt++)
                #pragma unroll
                for (int t = 0; t < 4; t++)
                    slot[(mt * 4 + t) * 32 + lane] =
                        make_float4(acc[mt][t][0], acc[mt][t][1],
                                    acc[mt][t][2], acc[mt][t][3]);
        }
        __syncthreads();
        if (kg == 0) {
            #pragma unroll
            for (int q = 0; q < 3; q++) {
                const float4* slot = scratch4 + (q * 4 + sub) * 256;
                #pragma unroll
                for (int mt = 0; mt < 2; mt++)
                    #pragma unroll
                    for (int t = 0; t < 4; t++) {
                        float4 v = slot[(mt * 4 + t) * 32 + lane];
                        acc[mt][t][0] += v.x; acc[mt][t][1] += v.y;
                        acc[mt][t][2] += v.z; acc[mt][t][3] += v.w;
                    }
            }
            #pragma unroll
            for (int mt = 0; mt < 2; mt++)
                #pragma unroll
                for (int t = 0; t < 4; t++) {
                    const int tile = ng * 4 + t;
                    if (tile < NT) {
                        const int n0 = tile * 8 + ((lane & 3) << 1);
                        const int rbase = m * 32 + mt * 16 + (lane >> 2);
                        #pragma unroll
                        for (int half = 0; half < 2; half++) {
                            const int n = n0 + half;
                            if (n < KOUT) {
                                const float bz = bs[l * KOUT + n];
                                #pragma unroll
                                for (int rr = 0; rr < 2; rr++) {
                                    float y = acc[mt][t][rr * 2 + half] + bz;
                                    y = (y > 0.f) ? y : 0.01f * y;
                                    A[(rbase + rr * 8) * RSE + width + n] =
                                        __float2half_rn(y);
                                }
                            }
                        }
                    }
                }
        }
        width += KOUT;
        __syncthreads();
    }

    // ---- final projection: out[r] = x . Wout + bout ----
    #pragma unroll
    for (int t = 0; t < 4; t++) {
        const int r = wid * 4 + t;
        float s = 0.f;
        for (int j = lane; j < FW; j += 32)
            s += __half2float(A[r * RSE + j]) * Wout[j];
        #pragma unroll
        for (int o = 16; o; o >>= 1) s += __shfl_xor_sync(0xffffffffu, s, o);
        if (lane == 0) out[cta * ROWS + r] = s + bout[0];
    }
}

extern "C" void kernel_launch(void* const* d_in, const int* in_sizes, int n_in,
                              void* d_out, int out_size) {
    const float* state = (const float*)d_in[0];
    const float* Ws    = (const float*)d_in[1];
    const float* bs    = (const float*)d_in[2];
    const float* Wout  = (const float*)d_in[3];
    const float* bout  = (const float*)d_in[4];
    float* out = (float*)d_out;

    const int B = in_sizes[0] / 16;   // 32768

    stage_w_kernel<<<(WFRAG_WORDS + 255) / 256, 256>>>(Ws);

    cudaFuncSetAttribute(value_model_mma_kernel,
                         cudaFuncAttributeMaxDynamicSharedMemorySize, SMEM_TOTAL);
    value_model_mma_kernel<<<B / ROWS, THREADS, SMEM_TOTAL>>>(state, bs, Wout, bout, out);
}

// round 15
// speedup vs baseline: 1.3877x; 1.0422x over previous
#include <cuda_runtime.h>
#include <cuda_fp16.h>
#include <cstdint>

#define NLAYERS 25
#define KOUT 50
#define FW 1266
#define ROWS 64
#define THREADS 512
#define MAXKS 76
#define NT 7
#define RSE 1272                         // fp16 elems/row (2544B, 16B-aligned)
#define A_BYTES (ROWS * RSE * 2)         // 162816
#define WOFF A_BYTES
#define KSB 1792                         // per-ks W block: 7 nt * 32 lanes * 8B
#define CK 16                            // ks per chunk
#define WBUF (CK * KSB)                  // 28672
#define SMEM_TOTAL (WOFF + 2 * WBUF)     // 220160

// W fragments: [layer][ks(76)][nt(7)][lane(32)][word(2)]; word = {bhi_r0, bhi_r1}
#define WFRAG_WORDS (NLAYERS * MAXKS * NT * 32 * 2)   // 851,200 (3.4 MB)
__device__ uint32_t g_wfrag[WFRAG_WORDS];

__device__ __forceinline__ uint32_t packh2(__half a, __half b) {
    return (uint32_t)__half_as_ushort(a) | ((uint32_t)__half_as_ushort(b) << 16);
}

// ---- prekernel: fp32 W -> fragment-ordered fp16 pairs (identical to R10/R13/R14) ----
__global__ void stage_w_kernel(const float* __restrict__ Ws) {
    int i = blockIdx.x * blockDim.x + threadIdx.x;
    if (i >= WFRAG_WORDS) return;
    int w = i;
    int reg  = w & 1;  w >>= 1;
    int ln   = w & 31; w >>= 5;
    int nt   = w % NT; w /= NT;
    int ks   = w % MAXKS;
    int layer = w / MAXKS;
    int n = nt * 8 + (ln >> 2);
    int k = ks * 16 + ((ln & 3) << 1) + reg * 8;   // k <= 1214, in-bounds
    float w0 = 0.f, w1 = 0.f;
    if (n < KOUT) {
        const float* p = Ws + ((size_t)layer * KOUT + n) * FW + k;
        w0 = p[0]; w1 = p[1];
    }
    g_wfrag[i] = packh2(__float2half_rn(w0), __float2half_rn(w1));
}

#define MMA(d, a, b0_, b1_) \
    asm volatile("mma.sync.aligned.m16n8k16.row.col.f32.f16.f16.f32 " \
        "{%0,%1,%2,%3},{%4,%5,%6,%7},{%8,%9},{%0,%1,%2,%3};" \
        : "+f"(d[0]), "+f"(d[1]), "+f"(d[2]), "+f"(d[3]) \
        : "r"(a[0]), "r"(a[1]), "r"(a[2]), "r"(a[3]), "r"(b0_), "r"(b1_))

#define LDSM4(r, addr) \
    asm volatile("ldmatrix.sync.aligned.m8n8.x4.shared.b16 {%0,%1,%2,%3}, [%4];" \
        : "=r"(r[0]), "=r"(r[1]), "=r"(r[2]), "=r"(r[3]) : "r"(addr))

__device__ __forceinline__ void cp16(uint32_t dst, const void* src) {
    asm volatile("cp.async.cg.shared.global [%0], [%1], 16;" :: "r"(dst), "l"(src));
}
__device__ __forceinline__ void barkg(int id) {
    asm volatile("bar.sync %0, 128;" :: "r"(id) : "memory");
}

__global__ void __launch_bounds__(THREADS, 1) value_model_mma_kernel(
    const float* __restrict__ state,
    const float* __restrict__ bs,
    const float* __restrict__ Wout,
    const float* __restrict__ bout,
    float* __restrict__ out)
{
    extern __shared__ char smraw[];
    __half* A = (__half*)smraw;
    const uint32_t sm_u32 = (uint32_t)__cvta_generic_to_shared(smraw);

    const int tid  = threadIdx.x;
    const int lane = tid & 31;
    const int wid  = tid >> 5;
    const int cta  = blockIdx.x;
    const int kg   = wid >> 2;         // 0..3: k-split within 16-ks chunk (4 ks each)
    const int m    = (wid >> 1) & 1;   // row-half: rows m*32 .. m*32+31
    const int ng   = wid & 1;          // n-group: tiles ng*4 .. (<7)
    const int sub  = wid & 3;          // (m, ng) id
    const int ltid = tid & 127;        // thread within kg group (warps contiguous)
    const int bid  = kg + 1;           // named barrier id for this kg group

    // ---- zero A plane ----
    {
        uint4 z = make_uint4(0u, 0u, 0u, 0u);
        uint4* p = (uint4*)smraw;
        for (int i = tid; i < A_BYTES / 16; i += THREADS) p[i] = z;
    }
    __syncthreads();

    // ---- initial state (64 x 16) ----
    for (int idx = tid; idx < ROWS * 16; idx += THREADS) {
        int r = idx >> 4, j = idx & 15;
        A[r * RSE + j] = __float2half_rn(state[(cta * ROWS + r) * 16 + j]);
    }
    __syncthreads();

    // ldmatrix base for this warp's two m16 tiles (rows m*32 and m*32+16)
    const uint32_t abase = sm_u32 + (uint32_t)((m * 32 + (lane & 15)) * RSE) * 2u
                                  + (uint32_t)(lane >> 4) * 16u;
    const uint32_t wsm = sm_u32 + WOFF;
    // single-wave kg-reduction scratch: 48KB, overlays both dead W buffers at epilogue
    float4* scratch4 = (float4*)(smraw + WOFF);

    // this kg group's slice inside a chunk: ksl in [4kg, 4kg+4)
    const uint32_t sl_off = (uint32_t)(kg * 4) * KSB;   // smem offset of slice in a buffer

    int width = 16;
    for (int l = 0; l < NLAYERS; l++) {
        const int nks = (width + 15) >> 4;
        const int nc  = (nks + CK - 1) / CK;

        float acc[2][4][4] = {};

        // ---- per-kg prologue: stage this group's slice of chunk 0 ----
        {
            const int ksn0 = (nks < CK) ? nks : CK;
            int scnt = ksn0 - kg * 4; scnt = (scnt < 0) ? 0 : ((scnt > 4) ? 4 : scnt);
            const char* src = (const char*)g_wfrag
                            + (size_t)(l * MAXKS + kg * 4) * KSB;
            const int nops = scnt * 112;
            for (int i = ltid; i < nops; i += 128)
                cp16(wsm + sl_off + i * 16, src + (size_t)i * 16);
            asm volatile("cp.async.commit_group;");
        }

        for (int c = 0; c < nc; c++) {
            // per-kg stage slice of chunk c+1
            if (c + 1 < nc) {
                const int rem = nks - (c + 1) * CK;
                const int ksn1 = (rem < CK) ? rem : CK;
                int scnt = ksn1 - kg * 4; scnt = (scnt < 0) ? 0 : ((scnt > 4) ? 4 : scnt);
                const char* src = (const char*)g_wfrag
                                + (size_t)(l * MAXKS + (c + 1) * CK + kg * 4) * KSB;
                uint32_t dst = wsm + (((c + 1) & 1) ? WBUF : 0) + sl_off;
                const int nops = scnt * 112;
                for (int i = ltid; i < nops; i += 128)
                    cp16(dst + i * 16, src + (size_t)i * 16);
                asm volatile("cp.async.commit_group;");
                asm volatile("cp.async.wait_group 1;");
            } else {
                asm volatile("cp.async.wait_group 0;");
            }
            barkg(bid);    // publish slice c within this kg group

            const uint32_t* wb = (const uint32_t*)(smraw + WOFF + ((c & 1) ? WBUF : 0));
            const int ksn = min(CK, nks - c * CK);

            #pragma unroll
            for (int i = 0; i < 4; i++) {
                const int ksl = kg * 4 + i;
                if (ksl < ksn) {
                    const int ks = c * CK + ksl;
                    uint32_t a0[4], a1[4];
                    const uint32_t ad = abase + (uint32_t)ks * 32u;
                    LDSM4(a0, ad);
                    LDSM4(a1, ad + 16u * RSE * 2u);
                    const uint32_t* wk = wb + ksl * 448;
                    #pragma unroll
                    for (int t = 0; t < 4; t++) {
                        const int tile = ng * 4 + t;
                        if (tile < NT) {
                            const uint2 b = *(const uint2*)(wk + tile * 64 + lane * 2);
                            MMA(acc[0][t], a0, b.x, b.y);
                            MMA(acc[1][t], a1, b.x, b.y);
                        }
                    }
                }
            }
            barkg(bid);    // this group's reads of slice c done (frees it for c+2)
        }

        // ---- epilogue (full-CTA): scratch overlays W buffers -> need all kg done ----
        __syncthreads();
        if (kg != 0) {
            float4* slot = scratch4 + ((kg - 1) * 4 + sub) * 256;
            #pragma unroll
            for (int mt = 0; mt < 2; mt++)
                #pragma unroll
                for (int t = 0; t < 4; t++)
                    slot[(mt * 4 + t) * 32 + lane] =
                        make_float4(acc[mt][t][0], acc[mt][t][1],
                                    acc[mt][t][2], acc[mt][t][3]);
        }
        __syncthreads();
        if (kg == 0) {
            #pragma unroll
            for (int q = 0; q < 3; q++) {
                const float4* slot = scratch4 + (q * 4 + sub) * 256;
                #pragma unroll
                for (int mt = 0; mt < 2; mt++)
                    #pragma unroll
                    for (int t = 0; t < 4; t++) {
                        float4 v = slot[(mt * 4 + t) * 32 + lane];
                        acc[mt][t][0] += v.x; acc[mt][t][1] += v.y;
                        acc[mt][t][2] += v.z; acc[mt][t][3] += v.w;
                    }
            }
            #pragma unroll
            for (int mt = 0; mt < 2; mt++)
                #pragma unroll
                for (int t = 0; t < 4; t++) {
                    const int tile = ng * 4 + t;
                    if (tile < NT) {
                        const int n0 = tile * 8 + ((lane & 3) << 1);
                        const int rbase = m * 32 + mt * 16 + (lane >> 2);
                        #pragma unroll
                        for (int half = 0; half < 2; half++) {
                            const int n = n0 + half;
                            if (n < KOUT) {
                                const float bz = bs[l * KOUT + n];
                                #pragma unroll
                                for (int rr = 0; rr < 2; rr++) {
                                    float y = acc[mt][t][rr * 2 + half] + bz;
                                    y = (y > 0.f) ? y : 0.01f * y;
                                    A[(rbase + rr * 8) * RSE + width + n] =
                                        __float2half_rn(y);
                                }
                            }
                        }
                    }
                }
        }
        width += KOUT;
        __syncthreads();   // layer end: A writes + scratch reads done before next prologue
    }

    // ---- final projection: out[r] = x . Wout + bout ----
    #pragma unroll
    for (int t = 0; t < 4; t++) {
        const int r = wid * 4 + t;
        float s = 0.f;
        for (int j = lane; j < FW; j += 32)
            s += __half2float(A[r * RSE + j]) * Wout[j];
        #pragma unroll
        for (int o = 16; o; o >>= 1) s += __shfl_xor_sync(0xffffffffu, s, o);
        if (lane == 0) out[cta * ROWS + r] = s + bout[0];
    }
}

extern "C" void kernel_launch(void* const* d_in, const int* in_sizes, int n_in,
                              void* d_out, int out_size) {
    const float* state = (const float*)d_in[0];
    const float* Ws    = (const float*)d_in[1];
    const float* bs    = (const float*)d_in[2];
    const float* Wout  = (const float*)d_in[3];
    const float* bout  = (const float*)d_in[4];
    float* out = (float*)d_out;

    const int B = in_sizes[0] / 16;   // 32768

    stage_w_kernel<<<(WFRAG_WORDS + 255) / 256, 256>>>(Ws);

    cudaFuncSetAttribute(value_model_mma_kernel,
                         cudaFuncAttributeMaxDynamicSharedMemorySize, SMEM_TOTAL);
    value_model_mma_kernel<<<B / ROWS, THREADS, SMEM_TOTAL>>>(state, bs, Wout, bout, out);
}